// round 13
// baseline (speedup 1.0000x reference)
#include <cuda_runtime.h>
#include <cuda_bf16.h>
#include <cstdint>
#include <cstddef>

#define DD      512
#define TSTEPS  256
#define BDIM    256
#define ZROWS   32768          // slices 0..127 kept as bf16 A-source

typedef unsigned short ushort_t;

// ---------------- static device storage (no allocs) ----------------
__device__ ushort_t g_zh[ZROWS * DD];        // z slices bf16 hi, [t][b][d]
__device__ ushort_t g_zl[ZROWS * DD];        // z slices bf16 lo
__device__ ushort_t g_z0h[BDIM * DD], g_z0l[BDIM * DD];
__device__ ushort_t g_pwh[8][DD * DD], g_pwl[8][DD * DD];    // K^(2^j) bf16
__device__ ushort_t g_pwth[8][DD * DD], g_pwtl[8][DD * DD];  // transposed [n][k]

// ---------------- helpers ----------------
__device__ __forceinline__ uint32_t smem_u32(const void* p) {
    uint32_t a;
    asm("{ .reg .u64 t; cvta.to.shared.u64 t, %1; cvt.u32.u64 %0, t; }"
        : "=r"(a) : "l"(p));
    return a;
}

#define CP16(dst, src) \
    asm volatile("cp.async.cg.shared.global [%0], [%1], 16;" \
                 :: "r"(dst), "l"(src) : "memory")
#define CP_COMMIT() asm volatile("cp.async.commit_group;" ::: "memory")
#define CP_WAIT0()  asm volatile("cp.async.wait_group 0;" ::: "memory")

#define LDSM4(R, a) \
    asm volatile("ldmatrix.sync.aligned.m8n8.x4.shared.b16 {%0,%1,%2,%3},[%4];" \
                 : "=r"((R)[0]), "=r"((R)[1]), "=r"((R)[2]), "=r"((R)[3]) : "r"(a))

#define MMA(C, A, b0v, b1v) \
    asm volatile("mma.sync.aligned.m16n8k16.row.col.f32.bf16.bf16.f32 " \
                 "{%0,%1,%2,%3},{%4,%5,%6,%7},{%8,%9},{%0,%1,%2,%3};" \
                 : "+f"((C)[0]), "+f"((C)[1]), "+f"((C)[2]), "+f"((C)[3]) \
                 : "r"((A)[0]), "r"((A)[1]), "r"((A)[2]), "r"((A)[3]), \
                   "r"(b0v), "r"(b1v))

__device__ __forceinline__ void split_bf16(float f, ushort_t& h, ushort_t& l) {
    __nv_bfloat16 bh = __float2bfloat16_rn(f);
    float fl = f - __bfloat162float(bh);
    __nv_bfloat16 bl = __float2bfloat16_rn(fl);
    h = *reinterpret_cast<ushort_t*>(&bh);
    l = *reinterpret_cast<ushort_t*>(&bl);
}

// ---------------- prep: K -> pw0 / pwT0 bf16 ; z0 -> z0 bf16 ----------------
__global__ void prep_kernel(const float* __restrict__ K, const float* __restrict__ z0)
{
    const int r = blockIdx.x;
    if (r < DD) {
        for (int c = threadIdx.x; c < DD; c += blockDim.x) {
            ushort_t h, l; split_bf16(K[r * DD + c], h, l);
            g_pwh[0][r * DD + c] = h;  g_pwl[0][r * DD + c] = l;
            g_pwth[0][c * DD + r] = h; g_pwtl[0][c * DD + r] = l;
        }
    } else {
        const int rr = r - DD;
        for (int c = threadIdx.x; c < DD; c += blockDim.x) {
            ushort_t h, l; split_bf16(z0[rr * DD + c], h, l);
            g_z0h[rr * DD + c] = h;  g_z0l[rr * DD + c] = l;
        }
    }
}

// ---------------- warp-MMA GEMM: D = A @ B^T, 3-term bf16 split -------------
// CTA tile 128 x 128, 8 warps (4m x 2n), warp tile 32 x 64, KC=64, 8 chunks.
// Stage: Ah/Al/Bh/Bl each 16KB = 64KB; 2 stages = 128KB -> 1 CTA/SM, regs free.
#define KC      64
#define CHUNKS  8
#define PLANE   16384
#define STAGE   65536

// rows [0,M1): A1 (z slices, contiguous), fp32 out + bf16 z copy
// rows >= M1:  A2 (power matrix) -> nxt bf16 planes (straight + transposed)
#define LOAD_CHUNK(chv, sv) do {                                               \
    const int kbase_ = (chv) * KC;                                             \
    _Pragma("unroll")                                                          \
    for (int p_ = 0; p_ < 4; ++p_) {                                           \
        const ushort_t* sp_ = srcs[p_];                                        \
        _Pragma("unroll")                                                      \
        for (int rep_ = 0; rep_ < 4; ++rep_) {                                 \
            const int c_   = tid + rep_ * 256;      /* 0..1023 */              \
            const int row_ = c_ >> 3;                                          \
            const int cc_  = (c_ & 7) * 8;                                     \
            const uint32_t dst_ = sbu + (uint32_t)(sv) * STAGE                 \
                + (uint32_t)p_ * PLANE + (uint32_t)(row_ * 128)                \
                + (((uint32_t)(cc_ * 2)) ^ ((uint32_t)(row_ & 7) << 4));       \
            CP16(dst_, sp_ + (size_t)row_ * DD + kbase_ + cc_);                \
        }                                                                      \
    }                                                                          \
} while (0)

__global__ void __launch_bounds__(256, 1)
gemm_tc(const ushort_t* __restrict__ a1h, const ushort_t* __restrict__ a1l,
        const ushort_t* __restrict__ a2h, const ushort_t* __restrict__ a2l,
        const ushort_t* __restrict__ bh,  const ushort_t* __restrict__ bl,
        float* __restrict__ outF,
        ushort_t* __restrict__ zH, ushort_t* __restrict__ zL,
        ushort_t* __restrict__ nxtH, ushort_t* __restrict__ nxtL,
        ushort_t* __restrict__ nxtTH, ushort_t* __restrict__ nxtTL,
        int M1, int tofs, int dstOfs)
{
    extern __shared__ char dsm[];
    char* sb = (char*)(((uintptr_t)dsm + 1023) & ~(uintptr_t)1023);
    const uint32_t sbu = smem_u32(sb);

    const int tid  = threadIdx.x;
    const int wid  = tid >> 5;
    const int lane = tid & 31;
    const int wm   = wid & 3;          // warp row (32 rows)
    const int wn   = wid >> 2;         // warp col (64 cols)
    const int rowBlk = blockIdx.x * 128;
    const int n0     = blockIdx.y * 128;

    // source row bases (CTA uniform: M1 % 128 == 0)
    const bool inA1 = (rowBlk < M1);
    const ushort_t* srcs[4];
    const size_t aOfs = (size_t)(inA1 ? rowBlk : (rowBlk - M1)) * DD;
    srcs[0] = (inA1 ? a1h : a2h) + aOfs;
    srcs[1] = (inA1 ? a1l : a2l) + aOfs;
    srcs[2] = bh + (size_t)n0 * DD;
    srcs[3] = bl + (size_t)n0 * DD;

    // ldmatrix per-lane address precompute (SW128: col ^ ((row&7)<<4))
    uint32_t aOff[2], aXor[2];
    {
        const int r0 = wm * 32 + (lane & 15);
        #pragma unroll
        for (int mt = 0; mt < 2; ++mt) {
            const int r = r0 + mt * 16;
            aOff[mt] = (uint32_t)(r * 128);
            aXor[mt] = (uint32_t)((r & 7) << 4);
        }
    }
    const uint32_t aColB = (uint32_t)((lane >> 4) * 16);
    uint32_t bOff[4], bXor[4];
    {
        const int r0 = wn * 64 + (lane & 7) + 8 * (lane >> 4);
        #pragma unroll
        for (int np = 0; np < 4; ++np) {
            const int r = r0 + np * 16;
            bOff[np] = (uint32_t)(r * 128);
            bXor[np] = (uint32_t)((r & 7) << 4);
        }
    }
    const uint32_t bColB = (uint32_t)(((lane >> 3) & 1) * 16);

    float acc[2][8][4];
    #pragma unroll
    for (int mt = 0; mt < 2; ++mt)
        #pragma unroll
        for (int nt = 0; nt < 8; ++nt)
            #pragma unroll
            for (int q = 0; q < 4; ++q) acc[mt][nt][q] = 0.f;

    LOAD_CHUNK(0, 0); CP_COMMIT();

    for (int ch = 0; ch < CHUNKS; ++ch) {
        CP_WAIT0();              // chunk ch resident
        __syncthreads();         // visible to all; all warps done with buf[(ch+1)&1]
        if (ch + 1 < CHUNKS) { LOAD_CHUNK(ch + 1, (ch + 1) & 1); CP_COMMIT(); }

        const uint32_t base = sbu + (uint32_t)(ch & 1) * STAGE;
        #pragma unroll
        for (int k16 = 0; k16 < 4; ++k16) {
            const uint32_t cA = (uint32_t)(k16 * 32) + aColB;
            const uint32_t cB = (uint32_t)(k16 * 32) + bColB;
            uint32_t ah[2][4], al[2][4], bhf[4][4], blf[4][4];
            #pragma unroll
            for (int mt = 0; mt < 2; ++mt) {
                LDSM4(ah[mt], base + 0 * PLANE + aOff[mt] + (cA ^ aXor[mt]));
                LDSM4(al[mt], base + 1 * PLANE + aOff[mt] + (cA ^ aXor[mt]));
            }
            #pragma unroll
            for (int np = 0; np < 4; ++np) {
                LDSM4(bhf[np], base + 2 * PLANE + bOff[np] + (cB ^ bXor[np]));
                LDSM4(blf[np], base + 3 * PLANE + bOff[np] + (cB ^ bXor[np]));
            }
            // term-major; per-acc order (hh, hl, lh) unchanged -> bitwise identical
            #pragma unroll
            for (int mt = 0; mt < 2; ++mt)        // hi * hi
                #pragma unroll
                for (int nt = 0; nt < 8; ++nt) {
                    const uint32_t* bp = &bhf[nt >> 1][(nt & 1) * 2];
                    MMA(acc[mt][nt], ah[mt], bp[0], bp[1]);
                }
            #pragma unroll
            for (int mt = 0; mt < 2; ++mt)        // hi * lo
                #pragma unroll
                for (int nt = 0; nt < 8; ++nt) {
                    const uint32_t* lp = &blf[nt >> 1][(nt & 1) * 2];
                    MMA(acc[mt][nt], ah[mt], lp[0], lp[1]);
                }
            #pragma unroll
            for (int mt = 0; mt < 2; ++mt)        // lo * hi
                #pragma unroll
                for (int nt = 0; nt < 8; ++nt) {
                    const uint32_t* bp = &bhf[nt >> 1][(nt & 1) * 2];
                    MMA(acc[mt][nt], al[mt], bp[0], bp[1]);
                }
        }
        __syncthreads();   // warps must finish LDSM on buf[ch&1] before it's reloaded
    }

    // epilogue: D row = lane>>2 (+8), col = 2*(lane&3)
    #pragma unroll
    for (int mt = 0; mt < 2; ++mt)
        #pragma unroll
        for (int nt = 0; nt < 8; ++nt) {
            const int rbase = rowBlk + wm * 32 + mt * 16 + (lane >> 2);
            const int col   = n0 + wn * 64 + nt * 8 + 2 * (lane & 3);
            #pragma unroll
            for (int half = 0; half < 2; ++half) {
                const int g = rbase + half * 8;
                const float c0 = acc[mt][nt][half * 2];
                const float c1 = acc[mt][nt][half * 2 + 1];
                ushort_t h0, l0, h1, l1;
                split_bf16(c0, h0, l0); split_bf16(c1, h1, l1);
                const uint32_t ph = (uint32_t)h0 | ((uint32_t)h1 << 16);
                const uint32_t pl = (uint32_t)l0 | ((uint32_t)l1 << 16);
                if (inA1) {
                    float2 v; v.x = c0; v.y = c1;
                    *reinterpret_cast<float2*>(
                        outF + ((size_t)(g & 255) * TSTEPS + (size_t)tofs + (g >> 8)) * DD
                             + col) = v;
                    const int zr = g + dstOfs;
                    if (zr < ZROWS) {
                        *reinterpret_cast<uint32_t*>(zH + (size_t)zr * DD + col) = ph;
                        *reinterpret_cast<uint32_t*>(zL + (size_t)zr * DD + col) = pl;
                    }
                } else {
                    const int r = g - M1;
                    const size_t o = (size_t)r * DD + col;
                    *reinterpret_cast<uint32_t*>(nxtH + o) = ph;
                    *reinterpret_cast<uint32_t*>(nxtL + o) = pl;
                    // fused transpose: [n][k] planes for next level's B operand
                    nxtTH[(size_t)col * DD + r]       = h0;
                    nxtTH[(size_t)(col + 1) * DD + r] = h1;
                    nxtTL[(size_t)col * DD + r]       = l0;
                    nxtTL[(size_t)(col + 1) * DD + r] = l1;
                }
            }
        }
}

// ---------------- host ----------------
extern "C" void kernel_launch(void* const* d_in, const int* in_sizes, int n_in,
                              void* d_out, int out_size)
{
    const float* z0 = (const float*)d_in[0];
    const float* K  = (const float*)d_in[1];
    float* out = (float*)d_out;

    ushort_t *zh, *zl, *z0h, *z0l, *pwh, *pwl, *pwth, *pwtl;
    cudaGetSymbolAddress((void**)&zh,   g_zh);
    cudaGetSymbolAddress((void**)&zl,   g_zl);
    cudaGetSymbolAddress((void**)&z0h,  g_z0h);
    cudaGetSymbolAddress((void**)&z0l,  g_z0l);
    cudaGetSymbolAddress((void**)&pwh,  g_pwh);
    cudaGetSymbolAddress((void**)&pwl,  g_pwl);
    cudaGetSymbolAddress((void**)&pwth, g_pwth);
    cudaGetSymbolAddress((void**)&pwtl, g_pwtl);

    const int SMEM = 2 * STAGE + 1024;   // 132 KB -> 1 CTA/SM
    cudaFuncSetAttribute(gemm_tc, cudaFuncAttributeMaxDynamicSharedMemorySize, SMEM);

    prep_kernel<<<DD + BDIM, 256>>>(K, z0);

    // G0: slice 0 = z0 @ K  (no squaring rows; nxt args unused)
    gemm_tc<<<dim3(BDIM / 128, 4), 256, SMEM>>>(
        z0h, z0l, z0h, z0l, pwth, pwtl,
        out, zh, zl, pwh, pwl, pwth, pwtl,
        /*M1=*/BDIM, /*tofs=*/0, /*dstOfs=*/0);

    // Level j: [slices 0..n-1] @ K^n -> slices n..2n-1 ; append K^n@K^n -> K^(2n)
    for (int j = 0; j < 8; ++j) {
        const int n  = 1 << j;
        const int M1 = BDIM * n;
        const int rows = M1 + ((j < 7) ? DD : 0);
        const size_t mo = (size_t)j * DD * DD;
        const size_t no = (size_t)(j < 7 ? j + 1 : 0) * DD * DD;
        gemm_tc<<<dim3(rows / 128, 4), 256, SMEM>>>(
            zh, zl, pwh + mo, pwl + mo, pwth + mo, pwtl + mo,
            out, zh, zl,
            pwh + no, pwl + no, pwth + no, pwtl + no,
            M1, /*tofs=*/n, /*dstOfs=*/M1);
    }
}

// round 14
// speedup vs baseline: 1.1015x; 1.1015x over previous
#include <cuda_runtime.h>
#include <cuda_bf16.h>
#include <cstdint>
#include <cstddef>

#define DD      512
#define TSTEPS  256
#define BDIM    256
#define ZROWS   32768          // slices 0..127 kept as bf16 A-source

typedef unsigned short ushort_t;

// ---------------- static device storage (no allocs) ----------------
__device__ ushort_t g_zh[ZROWS * DD];        // z slices bf16 hi, [t][b][d]
__device__ ushort_t g_zl[ZROWS * DD];        // z slices bf16 lo
__device__ ushort_t g_z0h[BDIM * DD], g_z0l[BDIM * DD];
__device__ ushort_t g_pwh[8][DD * DD], g_pwl[8][DD * DD];    // K^(2^j) bf16
__device__ ushort_t g_pwth[8][DD * DD], g_pwtl[8][DD * DD];  // transposed [n][k]

// ---------------- helpers ----------------
__device__ __forceinline__ uint32_t smem_u32(const void* p) {
    uint32_t a;
    asm("{ .reg .u64 t; cvta.to.shared.u64 t, %1; cvt.u32.u64 %0, t; }"
        : "=r"(a) : "l"(p));
    return a;
}

#define CP16(dst, src) \
    asm volatile("cp.async.cg.shared.global [%0], [%1], 16;" \
                 :: "r"(dst), "l"(src) : "memory")
#define CP_COMMIT() asm volatile("cp.async.commit_group;" ::: "memory")
#define CP_WAIT2()  asm volatile("cp.async.wait_group 2;" ::: "memory")

#define LDSM4(R, a) \
    asm volatile("ldmatrix.sync.aligned.m8n8.x4.shared.b16 {%0,%1,%2,%3},[%4];" \
                 : "=r"((R)[0]), "=r"((R)[1]), "=r"((R)[2]), "=r"((R)[3]) : "r"(a))

#define MMA(C, A, b0v, b1v) \
    asm volatile("mma.sync.aligned.m16n8k16.row.col.f32.bf16.bf16.f32 " \
                 "{%0,%1,%2,%3},{%4,%5,%6,%7},{%8,%9},{%0,%1,%2,%3};" \
                 : "+f"((C)[0]), "+f"((C)[1]), "+f"((C)[2]), "+f"((C)[3]) \
                 : "r"((A)[0]), "r"((A)[1]), "r"((A)[2]), "r"((A)[3]), \
                   "r"(b0v), "r"(b1v))

__device__ __forceinline__ void split_bf16(float f, ushort_t& h, ushort_t& l) {
    __nv_bfloat16 bh = __float2bfloat16_rn(f);
    float fl = f - __bfloat162float(bh);
    __nv_bfloat16 bl = __float2bfloat16_rn(fl);
    h = *reinterpret_cast<ushort_t*>(&bh);
    l = *reinterpret_cast<ushort_t*>(&bl);
}

// ---------------- prep: K -> pw0 / pwT0 bf16 ; z0 -> z0 bf16 ----------------
__global__ void prep_kernel(const float* __restrict__ K, const float* __restrict__ z0)
{
    const int r = blockIdx.x;
    if (r < DD) {
        for (int c = threadIdx.x; c < DD; c += blockDim.x) {
            ushort_t h, l; split_bf16(K[r * DD + c], h, l);
            g_pwh[0][r * DD + c] = h;  g_pwl[0][r * DD + c] = l;
            g_pwth[0][c * DD + r] = h; g_pwtl[0][c * DD + r] = l;
        }
    } else {
        const int rr = r - DD;
        for (int c = threadIdx.x; c < DD; c += blockDim.x) {
            ushort_t h, l; split_bf16(z0[rr * DD + c], h, l);
            g_z0h[rr * DD + c] = h;  g_z0l[rr * DD + c] = l;
        }
    }
}

// ---------------- warp-MMA GEMM: D = A @ B^T, 3-term bf16 split -------------
// CTA tile 64 x 128, 8 warps (2m x 4n), warp tile 32 x 32.
// KC=32, 16 chunks, 4 smem stages, 1 sync per chunk.
// Smem row = 128B: [64B hi | 64B lo] for one k32 of one matrix row (SW128).
// Stage: A 64 rows x 128B = 8KB @0 ; B 128 rows x 128B = 16KB @8192 -> 24KB.
#define KC      32
#define CHUNKS  16
#define OFF_B   8192
#define STAGE   24576
#define NST     4

// rows [0,M1): A1 (z slices, contiguous), fp32 out + bf16 z copy
// rows >= M1:  A2 (power matrix) -> nxt bf16 planes (straight + transposed)
#define LOAD_CHUNK(chv, sv) do {                                               \
    const int kbase_ = (chv) * KC;                                             \
    const uint32_t stb_ = sbu + (uint32_t)(sv) * STAGE;                        \
    /* A: 512 16B-ops, 2 per thread */                                         \
    _Pragma("unroll")                                                          \
    for (int rep_ = 0; rep_ < 2; ++rep_) {                                     \
        const int o_    = tid + rep_ * 256;                                    \
        const int row_  = o_ >> 3;                                             \
        const int pc_   = o_ & 7;                                              \
        const ushort_t* sp_ = (pc_ < 4) ? srcs[0] : srcs[1];                   \
        const int col_  = (pc_ & 3) * 16 + ((pc_ < 4) ? 0 : 64);               \
        const uint32_t dst_ = stb_ + (uint32_t)(row_ * 128)                    \
            + (((uint32_t)col_) ^ ((uint32_t)(row_ & 7) << 4));                \
        CP16(dst_, sp_ + (size_t)row_ * DD + kbase_ + (pc_ & 3) * 8);          \
    }                                                                          \
    /* B: 1024 16B-ops, 4 per thread */                                        \
    _Pragma("unroll")                                                          \
    for (int rep_ = 0; rep_ < 4; ++rep_) {                                     \
        const int o_    = tid + rep_ * 256;                                    \
        const int row_  = o_ >> 3;                                             \
        const int pc_   = o_ & 7;                                              \
        const ushort_t* sp_ = (pc_ < 4) ? srcs[2] : srcs[3];                   \
        const int col_  = (pc_ & 3) * 16 + ((pc_ < 4) ? 0 : 64);               \
        const uint32_t dst_ = stb_ + OFF_B + (uint32_t)(row_ * 128)            \
            + (((uint32_t)col_) ^ ((uint32_t)(row_ & 7) << 4));                \
        CP16(dst_, sp_ + (size_t)row_ * DD + kbase_ + (pc_ & 3) * 8);          \
    }                                                                          \
} while (0)

__global__ void __launch_bounds__(256, 2)
gemm_tc(const ushort_t* __restrict__ a1h, const ushort_t* __restrict__ a1l,
        const ushort_t* __restrict__ a2h, const ushort_t* __restrict__ a2l,
        const ushort_t* __restrict__ bh,  const ushort_t* __restrict__ bl,
        float* __restrict__ outF,
        ushort_t* __restrict__ zH, ushort_t* __restrict__ zL,
        ushort_t* __restrict__ nxtH, ushort_t* __restrict__ nxtL,
        ushort_t* __restrict__ nxtTH, ushort_t* __restrict__ nxtTL,
        int M1, int tofs, int dstOfs)
{
    extern __shared__ char dsm[];
    char* sb = (char*)(((uintptr_t)dsm + 1023) & ~(uintptr_t)1023);
    const uint32_t sbu = smem_u32(sb);

    const int tid  = threadIdx.x;
    const int wid  = tid >> 5;
    const int lane = tid & 31;
    const int wm   = wid & 1;          // warp row (32 rows)
    const int wn   = wid >> 1;         // warp col (32 cols)
    const int rowBlk = blockIdx.x * 64;
    const int n0     = blockIdx.y * 128;

    // source row bases (CTA uniform: M1 % 64 == 0)
    const bool inA1 = (rowBlk < M1);
    const ushort_t* srcs[4];
    const size_t aOfs = (size_t)(inA1 ? rowBlk : (rowBlk - M1)) * DD;
    srcs[0] = (inA1 ? a1h : a2h) + aOfs;
    srcs[1] = (inA1 ? a1l : a2l) + aOfs;
    srcs[2] = bh + (size_t)n0 * DD;
    srcs[3] = bl + (size_t)n0 * DD;

    // ldmatrix per-lane address precompute (SW128: off ^ ((row&7)<<4))
    uint32_t aOff[2], aXor[2];
    {
        const int r0 = wm * 32 + (lane & 15);
        #pragma unroll
        for (int mt = 0; mt < 2; ++mt) {
            const int r = r0 + mt * 16;
            aOff[mt] = (uint32_t)(r * 128);
            aXor[mt] = (uint32_t)((r & 7) << 4);
        }
    }
    const uint32_t aColB = (uint32_t)((lane >> 4) * 16);
    uint32_t bOff[2], bXor[2];
    {
        const int r0 = wn * 32 + (lane & 7) + 8 * (lane >> 4);
        #pragma unroll
        for (int np = 0; np < 2; ++np) {
            const int r = r0 + np * 16;
            bOff[np] = (uint32_t)(r * 128);
            bXor[np] = (uint32_t)((r & 7) << 4);
        }
    }
    const uint32_t bColB = (uint32_t)(((lane >> 3) & 1) * 16);

    float acc[2][4][4];
    #pragma unroll
    for (int mt = 0; mt < 2; ++mt)
        #pragma unroll
        for (int nt = 0; nt < 4; ++nt)
            #pragma unroll
            for (int q = 0; q < 4; ++q) acc[mt][nt][q] = 0.f;

    // prologue: 3 chunks in flight
    LOAD_CHUNK(0, 0); CP_COMMIT();
    LOAD_CHUNK(1, 1); CP_COMMIT();
    LOAD_CHUNK(2, 2); CP_COMMIT();

    for (int ch = 0; ch < CHUNKS; ++ch) {
        CP_WAIT2();              // chunk ch arrived (2 newer groups may be in flight)
        __syncthreads();         // data visible; all warps done with buf (ch+3)&3

        if (ch + 3 < CHUNKS) { LOAD_CHUNK(ch + 3, (ch + 3) & 3); }
        CP_COMMIT();             // unconditional (possibly empty) to keep group count

        const uint32_t base = sbu + (uint32_t)(ch & 3) * STAGE;
        #pragma unroll
        for (int k16 = 0; k16 < 2; ++k16) {
            const uint32_t cA = (uint32_t)(k16 * 32) + aColB;
            const uint32_t cB = (uint32_t)(k16 * 32) + bColB;
            uint32_t ah[2][4], al[2][4], bhf[2][4], blf[2][4];
            #pragma unroll
            for (int mt = 0; mt < 2; ++mt) {
                LDSM4(ah[mt], base + aOff[mt] + (cA ^ aXor[mt]));
                LDSM4(al[mt], base + aOff[mt] + ((cA + 64u) ^ aXor[mt]));
            }
            #pragma unroll
            for (int np = 0; np < 2; ++np) {
                LDSM4(bhf[np], base + OFF_B + bOff[np] + (cB ^ bXor[np]));
                LDSM4(blf[np], base + OFF_B + bOff[np] + ((cB + 64u) ^ bXor[np]));
            }
            // term-major; per-acc order (hh, hl, lh) unchanged -> bitwise identical
            #pragma unroll
            for (int mt = 0; mt < 2; ++mt)        // hi * hi
                #pragma unroll
                for (int nt = 0; nt < 4; ++nt) {
                    const uint32_t* bp = &bhf[nt >> 1][(nt & 1) * 2];
                    MMA(acc[mt][nt], ah[mt], bp[0], bp[1]);
                }
            #pragma unroll
            for (int mt = 0; mt < 2; ++mt)        // hi * lo
                #pragma unroll
                for (int nt = 0; nt < 4; ++nt) {
                    const uint32_t* lp = &blf[nt >> 1][(nt & 1) * 2];
                    MMA(acc[mt][nt], ah[mt], lp[0], lp[1]);
                }
            #pragma unroll
            for (int mt = 0; mt < 2; ++mt)        // lo * hi
                #pragma unroll
                for (int nt = 0; nt < 4; ++nt) {
                    const uint32_t* bp = &bhf[nt >> 1][(nt & 1) * 2];
                    MMA(acc[mt][nt], al[mt], bp[0], bp[1]);
                }
        }
    }

    // epilogue: D row = lane>>2 (+8), col = 2*(lane&3)
    #pragma unroll
    for (int mt = 0; mt < 2; ++mt)
        #pragma unroll
        for (int nt = 0; nt < 4; ++nt) {
            const int rbase = rowBlk + wm * 32 + mt * 16 + (lane >> 2);
            const int col   = n0 + wn * 32 + nt * 8 + 2 * (lane & 3);
            #pragma unroll
            for (int half = 0; half < 2; ++half) {
                const int g = rbase + half * 8;
                const float c0 = acc[mt][nt][half * 2];
                const float c1 = acc[mt][nt][half * 2 + 1];
                ushort_t h0, l0, h1, l1;
                split_bf16(c0, h0, l0); split_bf16(c1, h1, l1);
                const uint32_t ph = (uint32_t)h0 | ((uint32_t)h1 << 16);
                const uint32_t pl = (uint32_t)l0 | ((uint32_t)l1 << 16);
                if (inA1) {
                    float2 v; v.x = c0; v.y = c1;
                    *reinterpret_cast<float2*>(
                        outF + ((size_t)(g & 255) * TSTEPS + (size_t)tofs + (g >> 8)) * DD
                             + col) = v;
                    const int zr = g + dstOfs;
                    if (zr < ZROWS) {
                        *reinterpret_cast<uint32_t*>(zH + (size_t)zr * DD + col) = ph;
                        *reinterpret_cast<uint32_t*>(zL + (size_t)zr * DD + col) = pl;
                    }
                } else {
                    const int r = g - M1;
                    const size_t o = (size_t)r * DD + col;
                    *reinterpret_cast<uint32_t*>(nxtH + o) = ph;
                    *reinterpret_cast<uint32_t*>(nxtL + o) = pl;
                    // fused transpose: [n][k] planes for next level's B operand
                    nxtTH[(size_t)col * DD + r]       = h0;
                    nxtTH[(size_t)(col + 1) * DD + r] = h1;
                    nxtTL[(size_t)col * DD + r]       = l0;
                    nxtTL[(size_t)(col + 1) * DD + r] = l1;
                }
            }
        }
}

// ---------------- host ----------------
extern "C" void kernel_launch(void* const* d_in, const int* in_sizes, int n_in,
                              void* d_out, int out_size)
{
    const float* z0 = (const float*)d_in[0];
    const float* K  = (const float*)d_in[1];
    float* out = (float*)d_out;

    ushort_t *zh, *zl, *z0h, *z0l, *pwh, *pwl, *pwth, *pwtl;
    cudaGetSymbolAddress((void**)&zh,   g_zh);
    cudaGetSymbolAddress((void**)&zl,   g_zl);
    cudaGetSymbolAddress((void**)&z0h,  g_z0h);
    cudaGetSymbolAddress((void**)&z0l,  g_z0l);
    cudaGetSymbolAddress((void**)&pwh,  g_pwh);
    cudaGetSymbolAddress((void**)&pwl,  g_pwl);
    cudaGetSymbolAddress((void**)&pwth, g_pwth);
    cudaGetSymbolAddress((void**)&pwtl, g_pwtl);

    const int SMEM = NST * STAGE + 1024;   // 99328 B -> 2 CTAs/SM
    cudaFuncSetAttribute(gemm_tc, cudaFuncAttributeMaxDynamicSharedMemorySize, SMEM);

    prep_kernel<<<DD + BDIM, 256>>>(K, z0);

    // G0: slice 0 = z0 @ K  (no squaring rows; nxt args unused)
    gemm_tc<<<dim3(BDIM / 64, 4), 256, SMEM>>>(
        z0h, z0l, z0h, z0l, pwth, pwtl,
        out, zh, zl, pwh, pwl, pwth, pwtl,
        /*M1=*/BDIM, /*tofs=*/0, /*dstOfs=*/0);

    // Level j: [slices 0..n-1] @ K^n -> slices n..2n-1 ; append K^n@K^n -> K^(2n)
    for (int j = 0; j < 8; ++j) {
        const int n  = 1 << j;
        const int M1 = BDIM * n;
        const int rows = M1 + ((j < 7) ? DD : 0);
        const size_t mo = (size_t)j * DD * DD;
        const size_t no = (size_t)(j < 7 ? j + 1 : 0) * DD * DD;
        gemm_tc<<<dim3(rows / 64, 4), 256, SMEM>>>(
            zh, zl, pwh + mo, pwl + mo, pwth + mo, pwtl + mo,
            out, zh, zl,
            pwh + no, pwl + no, pwth + no, pwtl + no,
            M1, /*tofs=*/n, /*dstOfs=*/M1);
    }
}

// round 15
// speedup vs baseline: 1.2893x; 1.1705x over previous
#include <cuda_runtime.h>
#include <cuda_bf16.h>
#include <cstdint>
#include <cstddef>

#define DD      512
#define TSTEPS  256
#define BDIM    256
#define ZROWS   32768          // slices 0..127 kept as bf16 A-source

typedef unsigned short ushort_t;

// ---------------- static device storage (no allocs) ----------------
__device__ ushort_t g_zh[ZROWS * DD];        // z slices bf16 hi, [t][b][d]
__device__ ushort_t g_zl[ZROWS * DD];        // z slices bf16 lo
__device__ ushort_t g_z0h[BDIM * DD], g_z0l[BDIM * DD];
__device__ ushort_t g_pwh[8][DD * DD], g_pwl[8][DD * DD];    // K^(2^j) bf16
__device__ ushort_t g_pwth[8][DD * DD], g_pwtl[8][DD * DD];  // transposed [n][k]

// ---------------- helpers ----------------
__device__ __forceinline__ uint32_t smem_u32(const void* p) {
    uint32_t a;
    asm("{ .reg .u64 t; cvta.to.shared.u64 t, %1; cvt.u32.u64 %0, t; }"
        : "=r"(a) : "l"(p));
    return a;
}

#define CP16(dst, src) \
    asm volatile("cp.async.cg.shared.global [%0], [%1], 16;" \
                 :: "r"(dst), "l"(src) : "memory")
#define CP_COMMIT() asm volatile("cp.async.commit_group;" ::: "memory")
#define CP_WAIT0()  asm volatile("cp.async.wait_group 0;" ::: "memory")

#define LDSM4(R, a) \
    asm volatile("ldmatrix.sync.aligned.m8n8.x4.shared.b16 {%0,%1,%2,%3},[%4];" \
                 : "=r"((R)[0]), "=r"((R)[1]), "=r"((R)[2]), "=r"((R)[3]) : "r"(a))

#define MMA(C, A, b0v, b1v) \
    asm volatile("mma.sync.aligned.m16n8k16.row.col.f32.bf16.bf16.f32 " \
                 "{%0,%1,%2,%3},{%4,%5,%6,%7},{%8,%9},{%0,%1,%2,%3};" \
                 : "+f"((C)[0]), "+f"((C)[1]), "+f"((C)[2]), "+f"((C)[3]) \
                 : "r"((A)[0]), "r"((A)[1]), "r"((A)[2]), "r"((A)[3]), \
                   "r"(b0v), "r"(b1v))

__device__ __forceinline__ void split_bf16(float f, ushort_t& h, ushort_t& l) {
    __nv_bfloat16 bh = __float2bfloat16_rn(f);
    float fl = f - __bfloat162float(bh);
    __nv_bfloat16 bl = __float2bfloat16_rn(fl);
    h = *reinterpret_cast<ushort_t*>(&bh);
    l = *reinterpret_cast<ushort_t*>(&bl);
}

// ---------------- prep: K -> pw0 / pwT0 bf16 ; z0 -> z0 bf16 ----------------
__global__ void prep_kernel(const float* __restrict__ K, const float* __restrict__ z0)
{
    const int r = blockIdx.x;
    if (r < DD) {
        for (int c = threadIdx.x; c < DD; c += blockDim.x) {
            ushort_t h, l; split_bf16(K[r * DD + c], h, l);
            g_pwh[0][r * DD + c] = h;  g_pwl[0][r * DD + c] = l;
            g_pwth[0][c * DD + r] = h; g_pwtl[0][c * DD + r] = l;
        }
    } else {
        const int rr = r - DD;
        for (int c = threadIdx.x; c < DD; c += blockDim.x) {
            ushort_t h, l; split_bf16(z0[rr * DD + c], h, l);
            g_z0h[rr * DD + c] = h;  g_z0l[rr * DD + c] = l;
        }
    }
}

// ---------------- warp-MMA GEMM: D = A @ B^T, 3-term bf16 split -------------
// CTA tile TM x 128 (TM = 64 or 32), TM*4 threads, warps (TM/32)m x 4n,
// warp tile 32x32, KC=64, 8 chunks, double buffer, ONE sync per chunk.
#define KC      64
#define CHUNKS  8

#define LOAD_CHUNK(chv, sv) do {                                               \
    const int kbase_ = (chv) * KC;                                             \
    /* A planes (hi, lo): TM rows x 64 bf16 each, 2 reps per plane */          \
    _Pragma("unroll")                                                          \
    for (int p_ = 0; p_ < 2; ++p_) {                                           \
        const ushort_t* sp_ = srcs[p_];                                        \
        _Pragma("unroll")                                                      \
        for (int rep_ = 0; rep_ < 2; ++rep_) {                                 \
            const int o_   = tid + rep_ * THREADS;   /* 0..TM*8-1 */           \
            const int row_ = o_ >> 3;                                          \
            const int cc_  = (o_ & 7) * 8;                                     \
            const uint32_t dst_ = sbu + (uint32_t)(sv) * STAGE                 \
                + (uint32_t)p_ * PLANE_A + (uint32_t)(row_ * 128)              \
                + (((uint32_t)(cc_ * 2)) ^ ((uint32_t)(row_ & 7) << 4));       \
            CP16(dst_, sp_ + (size_t)row_ * DD + kbase_ + cc_);                \
        }                                                                      \
    }                                                                          \
    /* B planes (hi, lo): 128 rows x 64 bf16 each */                           \
    _Pragma("unroll")                                                          \
    for (int p_ = 0; p_ < 2; ++p_) {                                           \
        const ushort_t* sp_ = srcs[2 + p_];                                    \
        _Pragma("unroll")                                                      \
        for (int rep_ = 0; rep_ < BREP; ++rep_) {                              \
            const int o_   = tid + rep_ * THREADS;   /* 0..1023 */             \
            const int row_ = o_ >> 3;                                          \
            const int cc_  = (o_ & 7) * 8;                                     \
            const uint32_t dst_ = sbu + (uint32_t)(sv) * STAGE                 \
                + 2 * PLANE_A + (uint32_t)p_ * PLANE_B + (uint32_t)(row_ * 128)\
                + (((uint32_t)(cc_ * 2)) ^ ((uint32_t)(row_ & 7) << 4));       \
            CP16(dst_, sp_ + (size_t)row_ * DD + kbase_ + cc_);                \
        }                                                                      \
    }                                                                          \
} while (0)

template <int TM>
__global__ void __launch_bounds__(TM * 4, 2)
gemm_tc(const ushort_t* __restrict__ a1h, const ushort_t* __restrict__ a1l,
        const ushort_t* __restrict__ a2h, const ushort_t* __restrict__ a2l,
        const ushort_t* __restrict__ bh,  const ushort_t* __restrict__ bl,
        float* __restrict__ outF,
        ushort_t* __restrict__ zH, ushort_t* __restrict__ zL,
        ushort_t* __restrict__ nxtH, ushort_t* __restrict__ nxtL,
        ushort_t* __restrict__ nxtTH, ushort_t* __restrict__ nxtTL,
        int M1, int tofs, int dstOfs)
{
    constexpr int THREADS = TM * 4;
    constexpr int BREP    = 256 / TM;          // B loader reps
    constexpr int PLANE_A = TM * 128;          // one A plane (hi or lo)
    constexpr int PLANE_B = 16384;             // one B plane
    constexpr int STAGE   = 2 * PLANE_A + 2 * PLANE_B;
    constexpr int MWARPS  = TM / 32;

    extern __shared__ char dsm[];
    char* sb = (char*)(((uintptr_t)dsm + 1023) & ~(uintptr_t)1023);
    const uint32_t sbu = smem_u32(sb);

    const int tid  = threadIdx.x;
    const int wid  = tid >> 5;
    const int lane = tid & 31;
    const int wm   = wid & (MWARPS - 1);       // warp row (32 rows)
    const int wn   = wid / MWARPS;             // warp col (32 cols)
    const int rowBlk = blockIdx.x * TM;
    const int n0     = blockIdx.y * 128;

    // source row bases (CTA uniform: M1 % TM == 0)
    const bool inA1 = (rowBlk < M1);
    const ushort_t* srcs[4];
    const size_t aOfs = (size_t)(inA1 ? rowBlk : (rowBlk - M1)) * DD;
    srcs[0] = (inA1 ? a1h : a2h) + aOfs;
    srcs[1] = (inA1 ? a1l : a2l) + aOfs;
    srcs[2] = bh + (size_t)n0 * DD;
    srcs[3] = bl + (size_t)n0 * DD;

    // ldmatrix per-lane address precompute (SW128: col ^ ((row&7)<<4))
    uint32_t aOff[2], aXor[2];
    {
        const int r0 = wm * 32 + (lane & 15);
        #pragma unroll
        for (int mt = 0; mt < 2; ++mt) {
            const int r = r0 + mt * 16;
            aOff[mt] = (uint32_t)(r * 128);
            aXor[mt] = (uint32_t)((r & 7) << 4);
        }
    }
    const uint32_t aColB = (uint32_t)((lane >> 4) * 16);
    uint32_t bOff[2], bXor[2];
    {
        const int r0 = wn * 32 + (lane & 7) + 8 * (lane >> 4);
        #pragma unroll
        for (int np = 0; np < 2; ++np) {
            const int r = r0 + np * 16;
            bOff[np] = (uint32_t)(r * 128);
            bXor[np] = (uint32_t)((r & 7) << 4);
        }
    }
    const uint32_t bColB = (uint32_t)(((lane >> 3) & 1) * 16);

    float acc[2][4][4];
    #pragma unroll
    for (int mt = 0; mt < 2; ++mt)
        #pragma unroll
        for (int nt = 0; nt < 4; ++nt)
            #pragma unroll
            for (int q = 0; q < 4; ++q) acc[mt][nt][q] = 0.f;

    LOAD_CHUNK(0, 0); CP_COMMIT();

    for (int ch = 0; ch < CHUNKS; ++ch) {
        CP_WAIT0();              // chunk ch arrived (sole outstanding group)
        __syncthreads();         // data visible; every warp finished compute(ch-1)
                                 // -> buffer (ch+1)&1 free to overwrite
        if (ch + 1 < CHUNKS) { LOAD_CHUNK(ch + 1, (ch + 1) & 1); CP_COMMIT(); }

        const uint32_t base = sbu + (uint32_t)(ch & 1) * STAGE;
        #pragma unroll
        for (int k16 = 0; k16 < 4; ++k16) {
            const uint32_t cA = (uint32_t)(k16 * 32) + aColB;
            const uint32_t cB = (uint32_t)(k16 * 32) + bColB;
            uint32_t ah[2][4], al[2][4], bhf[2][4], blf[2][4];
            #pragma unroll
            for (int mt = 0; mt < 2; ++mt) {
                LDSM4(ah[mt], base + 0 * PLANE_A + aOff[mt] + (cA ^ aXor[mt]));
                LDSM4(al[mt], base + 1 * PLANE_A + aOff[mt] + (cA ^ aXor[mt]));
            }
            #pragma unroll
            for (int np = 0; np < 2; ++np) {
                LDSM4(bhf[np], base + 2 * PLANE_A + 0 * PLANE_B + bOff[np] + (cB ^ bXor[np]));
                LDSM4(blf[np], base + 2 * PLANE_A + 1 * PLANE_B + bOff[np] + (cB ^ bXor[np]));
            }
            // term-major; per-acc order (hh, hl, lh) unchanged -> bitwise identical
            #pragma unroll
            for (int mt = 0; mt < 2; ++mt)        // hi * hi
                #pragma unroll
                for (int nt = 0; nt < 4; ++nt) {
                    const uint32_t* bp = &bhf[nt >> 1][(nt & 1) * 2];
                    MMA(acc[mt][nt], ah[mt], bp[0], bp[1]);
                }
            #pragma unroll
            for (int mt = 0; mt < 2; ++mt)        // hi * lo
                #pragma unroll
                for (int nt = 0; nt < 4; ++nt) {
                    const uint32_t* lp = &blf[nt >> 1][(nt & 1) * 2];
                    MMA(acc[mt][nt], ah[mt], lp[0], lp[1]);
                }
            #pragma unroll
            for (int mt = 0; mt < 2; ++mt)        // lo * hi
                #pragma unroll
                for (int nt = 0; nt < 4; ++nt) {
                    const uint32_t* bp = &bhf[nt >> 1][(nt & 1) * 2];
                    MMA(acc[mt][nt], al[mt], bp[0], bp[1]);
                }
        }
    }

    // epilogue: D row = lane>>2 (+8), col = 2*(lane&3)
    #pragma unroll
    for (int mt = 0; mt < 2; ++mt)
        #pragma unroll
        for (int nt = 0; nt < 4; ++nt) {
            const int rbase = rowBlk + wm * 32 + mt * 16 + (lane >> 2);
            const int col   = n0 + wn * 32 + nt * 8 + 2 * (lane & 3);
            #pragma unroll
            for (int half = 0; half < 2; ++half) {
                const int g = rbase + half * 8;
                const float c0 = acc[mt][nt][half * 2];
                const float c1 = acc[mt][nt][half * 2 + 1];
                ushort_t h0, l0, h1, l1;
                split_bf16(c0, h0, l0); split_bf16(c1, h1, l1);
                const uint32_t ph = (uint32_t)h0 | ((uint32_t)h1 << 16);
                const uint32_t pl = (uint32_t)l0 | ((uint32_t)l1 << 16);
                if (inA1) {
                    float2 v; v.x = c0; v.y = c1;
                    *reinterpret_cast<float2*>(
                        outF + ((size_t)(g & 255) * TSTEPS + (size_t)tofs + (g >> 8)) * DD
                             + col) = v;
                    const int zr = g + dstOfs;
                    if (zr < ZROWS) {
                        *reinterpret_cast<uint32_t*>(zH + (size_t)zr * DD + col) = ph;
                        *reinterpret_cast<uint32_t*>(zL + (size_t)zr * DD + col) = pl;
                    }
                } else {
                    const int r = g - M1;
                    const size_t o = (size_t)r * DD + col;
                    *reinterpret_cast<uint32_t*>(nxtH + o) = ph;
                    *reinterpret_cast<uint32_t*>(nxtL + o) = pl;
                    // fused transpose: [n][k] planes for next level's B operand
                    nxtTH[(size_t)col * DD + r]       = h0;
                    nxtTH[(size_t)(col + 1) * DD + r] = h1;
                    nxtTL[(size_t)col * DD + r]       = l0;
                    nxtTL[(size_t)(col + 1) * DD + r] = l1;
                }
            }
        }
}

// ---------------- host ----------------
extern "C" void kernel_launch(void* const* d_in, const int* in_sizes, int n_in,
                              void* d_out, int out_size)
{
    const float* z0 = (const float*)d_in[0];
    const float* K  = (const float*)d_in[1];
    float* out = (float*)d_out;

    ushort_t *zh, *zl, *z0h, *z0l, *pwh, *pwl, *pwth, *pwtl;
    cudaGetSymbolAddress((void**)&zh,   g_zh);
    cudaGetSymbolAddress((void**)&zl,   g_zl);
    cudaGetSymbolAddress((void**)&z0h,  g_z0h);
    cudaGetSymbolAddress((void**)&z0l,  g_z0l);
    cudaGetSymbolAddress((void**)&pwh,  g_pwh);
    cudaGetSymbolAddress((void**)&pwl,  g_pwl);
    cudaGetSymbolAddress((void**)&pwth, g_pwth);
    cudaGetSymbolAddress((void**)&pwtl, g_pwtl);

    const int SMEM64 = 2 * (2 * 64 * 128 + 32768) + 1024;   // 99328 -> 2 CTAs/SM
    const int SMEM32 = 2 * (2 * 32 * 128 + 32768) + 1024;   // 82944
    cudaFuncSetAttribute(gemm_tc<64>, cudaFuncAttributeMaxDynamicSharedMemorySize, SMEM64);
    cudaFuncSetAttribute(gemm_tc<32>, cudaFuncAttributeMaxDynamicSharedMemorySize, SMEM32);

    prep_kernel<<<DD + BDIM, 256>>>(K, z0);

    auto launch = [&](const ushort_t* A1h, const ushort_t* A1l,
                      const ushort_t* A2h, const ushort_t* A2l,
                      const ushort_t* Bh,  const ushort_t* Bl,
                      ushort_t* nH, ushort_t* nL, ushort_t* nTH, ushort_t* nTL,
                      int rows, int M1, int tofs, int dstOfs) {
        if ((rows / 64) * 4 < 148) {
            gemm_tc<32><<<dim3(rows / 32, 4), 128, SMEM32>>>(
                A1h, A1l, A2h, A2l, Bh, Bl, out, zh, zl,
                nH, nL, nTH, nTL, M1, tofs, dstOfs);
        } else {
            gemm_tc<64><<<dim3(rows / 64, 4), 256, SMEM64>>>(
                A1h, A1l, A2h, A2l, Bh, Bl, out, zh, zl,
                nH, nL, nTH, nTL, M1, tofs, dstOfs);
        }
    };

    // G0: slice 0 = z0 @ K  (no squaring rows; nxt args unused)
    launch(z0h, z0l, z0h, z0l, pwth, pwtl,
           pwh, pwl, pwth, pwtl, BDIM, BDIM, 0, 0);

    // Level j: [slices 0..n-1] @ K^n -> slices n..2n-1 ; append K^n@K^n -> K^(2n)
    for (int j = 0; j < 8; ++j) {
        const int n  = 1 << j;
        const int M1 = BDIM * n;
        const int rows = M1 + ((j < 7) ? DD : 0);
        const size_t mo = (size_t)j * DD * DD;
        const size_t no = (size_t)(j < 7 ? j + 1 : 0) * DD * DD;
        launch(zh, zl, pwh + mo, pwl + mo, pwth + mo, pwtl + mo,
               pwh + no, pwl + no, pwth + no, pwtl + no,
               rows, M1, n, M1);
    }
}